// round 12
// baseline (speedup 1.0000x reference)
#include <cuda_runtime.h>
#include <cuda_bf16.h>
#include <mma.h>
#include <cstdint>

using namespace nvcuda;

#define NUSER 50000
#define NITEM 100000
#define NNODE 150000
#define NPAD  150016          // multiple of 512 (293*512)
#define NB_SCAN 293
#define NNZ   2000000
#define D     80              // 64 light + 16 mm, fused (augmented)
#define BATCH 1024
#define NTAIL0 99968          // 781*128

#define FLAG_AGG 0x20000000
#define FLAG_PRE 0x40000000
#define VAL_MASK 0x0FFFFFFF

// ---------------- static device scratch (no cudaMalloc allowed) ----------------
// X1..X3 = propagation layers 1..3 (layer 0 = raw input embeddings, never materialized)
__device__ __align__(256) float g_X1[(size_t)NPAD * D];
__device__ __align__(256) float g_X2[(size_t)NPAD * D];
__device__ __align__(256) float g_X3[(size_t)NPAD * D];
__device__ int   g_cnt[NPAD];          // zero at launch entry; re-zeroed by k_scan
__device__ int   g_rowptr[NPAD + 1];
__device__ int   g_cursor[NPAD];
__device__ int   g_state[NB_SCAN];     // lookback states; reset by k_scan
__device__ int   g_ticket;             // reset by k_scan
__device__ int   g_done;               // reset by k_scan
__device__ int   g_ci[NNZ];
__device__ float g_cv[NNZ];
__device__ __align__(256) __nv_bfloat16 g_UA[BATCH * D];            // augmented users
__device__ __align__(256) __nv_bfloat16 g_IA[(size_t)NITEM * D];    // augmented items

__device__ __forceinline__ float sigmoidf(float x) {
    return 1.0f / (1.0f + __expf(-x));
}

// ---------------- CSR: count ----------------
__global__ void k_count(const int* __restrict__ rows) {
    int i = blockIdx.x * blockDim.x + threadIdx.x;
    if (i < NNZ) atomicAdd(&g_cnt[rows[i]], 1);
}

// ---------------- CSR: single-pass decoupled-lookback scan ----------------
// Also re-zeroes g_cnt and resets its own ticket/state/done for the next replay.
__global__ void __launch_bounds__(512) k_scan() {
    __shared__ int s[512];
    __shared__ int sh_bid, sh_exc, sh_reset;
    int t = threadIdx.x;
    if (t == 0) sh_bid = atomicAdd(&g_ticket, 1);   // ticket: bid order == schedule order
    __syncthreads();
    int bid = sh_bid;
    int i = bid * 512 + t;

    int v = g_cnt[i];
    g_cnt[i] = 0;                                   // re-zero for next launch
    s[t] = v;
    __syncthreads();
    #pragma unroll
    for (int off = 1; off < 512; off <<= 1) {
        int x = (t >= off) ? s[t - off] : 0;
        __syncthreads();
        s[t] += x;
        __syncthreads();
    }
    int incl = s[t];
    int total = s[511];

    if (t == 0)
        atomicExch(&g_state[bid], (bid == 0 ? FLAG_PRE : FLAG_AGG) | total);

    // warp-parallel lookback (warp 0)
    if (bid > 0 && t < 32) {
        int exc = 0;
        int j = bid - 1;
        while (true) {
            int idx = j - t;
            int st = (idx >= 0) ? atomicAdd(&g_state[idx], 0) : (FLAG_PRE | 0);
            if (__all_sync(0xFFFFFFFFu, st != 0)) {
                unsigned pm = __ballot_sync(0xFFFFFFFFu, (st & FLAG_PRE) != 0);
                int fp = pm ? (__ffs(pm) - 1) : 32;
                int contrib = (t <= fp) ? (st & VAL_MASK) : 0;
                #pragma unroll
                for (int o = 16; o; o >>= 1)
                    contrib += __shfl_xor_sync(0xFFFFFFFFu, contrib, o);
                exc += contrib;
                if (fp < 32) break;
                j -= 32;
            }
        }
        if (t == 0) {
            atomicExch(&g_state[bid], FLAG_PRE | ((exc + total) & VAL_MASK));
            sh_exc = exc;
        }
    } else if (t == 0) sh_exc = 0;
    __syncthreads();

    int rp = sh_exc + incl - v;      // global exclusive
    g_rowptr[i] = rp;
    g_cursor[i] = rp;
    if (i == NPAD - 1) g_rowptr[NPAD] = NNZ;

    // last block to finish resets scan metadata for next graph replay
    __syncthreads();
    if (t == 0) sh_reset = (atomicAdd(&g_done, 1) + 1 == NB_SCAN);
    __syncthreads();
    if (sh_reset) {
        for (int k = t; k < NB_SCAN; k += 512) g_state[k] = 0;
        if (t == 0) { g_ticket = 0; g_done = 0; }
    }
}

// ---------------- CSR: fill ----------------
__global__ void k_fill(const int* __restrict__ rows, const int* __restrict__ cols,
                       const float* __restrict__ vals) {
    int i = blockIdx.x * blockDim.x + threadIdx.x;
    if (i >= NNZ) return;
    int r = rows[i];
    int p = atomicAdd(&g_cursor[r], 1);
    g_ci[p] = cols[i];
    g_cv[p] = vals[i];
}

// ---------------- layer-0 SpMM: gather directly from input embeddings ----------------
__global__ void k_spmm0(const float* __restrict__ eu, const float* __restrict__ ei,
                        const float* __restrict__ mu, const float* __restrict__ mi) {
    int row = blockIdx.x * (blockDim.x >> 5) + (threadIdx.x >> 5);
    int lane = threadIdx.x & 31;
    int start = g_rowptr[row];
    int deg = g_rowptr[row + 1] - start;
    float a0 = 0.f, a1 = 0.f, a2 = 0.f;
    for (int e = 0; e < deg; e++) {
        int c = __ldg(&g_ci[start + e]);
        float v = __ldg(&g_cv[start + e]);
        const float *b64, *b16;
        if (c < NUSER) { b64 = eu + (size_t)c * 64; b16 = mu + (size_t)c * 16; }
        else { b64 = ei + (size_t)(c - NUSER) * 64; b16 = mi + (size_t)(c - NUSER) * 16; }
        a0 += v * __ldg(b64 + lane);
        a1 += v * __ldg(b64 + 32 + lane);
        if (lane < 16) a2 += v * __ldg(b16 + lane);
    }
    float* o = g_X1 + (size_t)row * D;
    o[lane] = a0;
    o[32 + lane] = a1;
    if (lane < 16) o[64 + lane] = a2;
}

// ---------------- layers 1-2 SpMM: R5-proven gather, one row per warp ----------------
__global__ void k_spmm(const float* __restrict__ Xin, float* __restrict__ Xout) {
    int row = blockIdx.x * (blockDim.x >> 5) + (threadIdx.x >> 5);
    int lane = threadIdx.x & 31;
    int start = g_rowptr[row];
    int deg = g_rowptr[row + 1] - start;
    float a0 = 0.f, a1 = 0.f, a2 = 0.f;
    for (int e = 0; e < deg; e++) {
        int c = __ldg(&g_ci[start + e]);
        float v = __ldg(&g_cv[start + e]);
        const float* xr = Xin + (size_t)c * D;
        a0 += v * __ldg(xr + lane);
        a1 += v * __ldg(xr + 32 + lane);
        if (lane < 16) a2 += v * __ldg(xr + 64 + lane);
    }
    float* o = Xout + (size_t)row * D;
    o[lane] = a0;
    o[32 + lane] = a1;
    if (lane < 16) o[64 + lane] = a2;
}

// ---------------- augmented user / item builders (bf16, /4 folded in) ----------------
__global__ void k_uaug(const int* __restrict__ users, const float* __restrict__ bias_user,
                       const float* __restrict__ eu, const float* __restrict__ mu) {
    int i = blockIdx.x * blockDim.x + threadIdx.x;
    if (i >= BATCH * D) return;
    int b = i / D, d = i % D;
    int u = users[b];
    float v;
    if (d < 64) {
        size_t o = (size_t)u * D;
        float sl = __ldg(eu + (size_t)u * 64 + d) + g_X1[o + d] + g_X2[o + d] + g_X3[o + d];
        size_t om = o + 64 + (d >> 2);
        float sm = __ldg(mu + (size_t)u * 16 + (d >> 2)) + g_X1[om] + g_X2[om] + g_X3[om];
        v = 0.25f * (sl + sm);
    } else if (d == 64) v = bias_user[u];
    else if (d == 65) v = 1.0f;
    else v = 0.0f;
    g_UA[i] = __float2bfloat16(v);
}

__global__ void k_iaug(const float* __restrict__ bias_item,
                       const float* __restrict__ ei, const float* __restrict__ mi) {
    int i = blockIdx.x * blockDim.x + threadIdx.x;
    if (i >= NITEM * D) return;
    int it = i / D, d = i % D;
    float v;
    if (d < 64) {
        size_t o = (size_t)(NUSER + it) * D;
        float sl = __ldg(ei + (size_t)it * 64 + d) + g_X1[o + d] + g_X2[o + d] + g_X3[o + d];
        size_t om = o + 64 + (d >> 2);
        float sm = __ldg(mi + (size_t)it * 16 + (d >> 2)) + g_X1[om] + g_X2[om] + g_X3[om];
        v = 0.25f * (sl + sm);
    } else if (d == 64) v = 1.0f;
    else if (d == 65) v = bias_item[it];
    else v = 0.0f;
    g_IA[i] = __float2bfloat16(v);
}

// ---------------- GEMM: [1024,80]bf16 x [N,80]bf16^T -> sigmoid -> f32 (R5-proven) ----------------
__global__ void __launch_bounds__(256) k_gemm(float* __restrict__ out) {
    __shared__ alignas(16) __nv_bfloat16 As[128][88];
    __shared__ alignas(16) __nv_bfloat16 Bs[128][88];
    int m0 = blockIdx.y * 128;
    int n0 = blockIdx.x * 128;
    int t = threadIdx.x;

    const uint4* ua = (const uint4*)g_UA;   // 10 uint4 per row (80 bf16 = 160B)
    const uint4* ia = (const uint4*)g_IA;
    #pragma unroll
    for (int idx = t; idx < 1280; idx += 256) {
        int r = idx / 10, c = idx % 10;
        *(uint4*)(&As[r][c * 8]) = ua[(size_t)(m0 + r) * 10 + c];
    }
    #pragma unroll
    for (int idx = t; idx < 1280; idx += 256) {
        int r = idx / 10, c = idx % 10;
        *(uint4*)(&Bs[r][c * 8]) = ia[(size_t)(n0 + r) * 10 + c];
    }
    __syncthreads();

    int w = t >> 5;
    int wm = (w >> 1) * 32;   // 0,32,64,96
    int wn = (w & 1) * 64;    // 0,64

    wmma::fragment<wmma::accumulator, 16, 16, 16, float> acc[2][4];
    #pragma unroll
    for (int i = 0; i < 2; i++)
        #pragma unroll
        for (int j = 0; j < 4; j++)
            wmma::fill_fragment(acc[i][j], 0.0f);

    #pragma unroll
    for (int k = 0; k < 80; k += 16) {
        wmma::fragment<wmma::matrix_a, 16, 16, 16, __nv_bfloat16, wmma::row_major> a[2];
        wmma::fragment<wmma::matrix_b, 16, 16, 16, __nv_bfloat16, wmma::col_major> b[4];
        #pragma unroll
        for (int i = 0; i < 2; i++)
            wmma::load_matrix_sync(a[i], &As[wm + 16 * i][0] + k, 88);
        #pragma unroll
        for (int j = 0; j < 4; j++)
            wmma::load_matrix_sync(b[j], &Bs[wn + 16 * j][0] + k, 88);
        #pragma unroll
        for (int i = 0; i < 2; i++)
            #pragma unroll
            for (int j = 0; j < 4; j++)
                wmma::mma_sync(acc[i][j], a[i], b[j], acc[i][j]);
    }

    #pragma unroll
    for (int i = 0; i < 2; i++) {
        #pragma unroll
        for (int j = 0; j < 4; j++) {
            #pragma unroll
            for (int e = 0; e < acc[i][j].num_elements; e++)
                acc[i][j].x[e] = sigmoidf(acc[i][j].x[e]);
            wmma::store_matrix_sync(
                out + (size_t)(m0 + wm + 16 * i) * NITEM + (n0 + wn + 16 * j),
                acc[i][j], NITEM, wmma::mem_row_major);
        }
    }
}

// ---------------- tail: columns [99968, 100000) ----------------
__global__ void k_tail(float* __restrict__ out) {
    int i = blockIdx.x * blockDim.x + threadIdx.x;
    if (i >= BATCH * 32) return;
    int b = i >> 5, j = i & 31;
    int n = NTAIL0 + j;
    const __nv_bfloat16* u = g_UA + (size_t)b * D;
    const __nv_bfloat16* v = g_IA + (size_t)n * D;
    float s = 0.f;
    #pragma unroll
    for (int k = 0; k < D; k++)
        s += __bfloat162float(u[k]) * __bfloat162float(v[k]);
    out[(size_t)b * NITEM + n] = sigmoidf(s);
}

// ---------------- launcher ----------------
extern "C" void kernel_launch(void* const* d_in, const int* in_sizes, int n_in,
                              void* d_out, int out_size) {
    const float* emb_user  = (const float*)d_in[0];
    const float* emb_item  = (const float*)d_in[1];
    const float* bias_user = (const float*)d_in[2];
    const float* bias_item = (const float*)d_in[3];
    const float* mm_user   = (const float*)d_in[4];
    const float* mm_item   = (const float*)d_in[5];
    const float* vals      = (const float*)d_in[6];
    const int*   users     = (const int*)d_in[7];
    const int*   rows      = (const int*)d_in[8];
    const int*   cols      = (const int*)d_in[9];
    float* out = (float*)d_out;

    // CSR build: 3 launches (cnt is zero on entry; k_scan re-zeroes it + resets itself)
    k_count<<<(NNZ + 255) / 256, 256>>>(rows);
    k_scan<<<NB_SCAN, 512>>>();
    k_fill<<<(NNZ + 255) / 256, 256>>>(rows, cols, vals);

    // 3 propagation layers; layer 0 gathers straight from input embeddings
    k_spmm0<<<NPAD / 8, 256>>>(emb_user, emb_item, mm_user, mm_item);   // <- ncu capture slot
    k_spmm<<<NPAD / 8, 256>>>(g_X1, g_X2);
    k_spmm<<<NPAD / 8, 256>>>(g_X2, g_X3);

    // augmented embeddings (layer-0 term read from raw inputs)
    k_uaug<<<(BATCH * D + 255) / 256, 256>>>(users, bias_user, emb_user, mm_user);
    k_iaug<<<(NITEM * D + 255) / 256, 256>>>(bias_item, emb_item, mm_item);

    // main GEMM + tail
    dim3 grid(NTAIL0 / 128, BATCH / 128);
    k_gemm<<<grid, 256>>>(out);
    k_tail<<<(BATCH * 32 + 255) / 256, 256>>>(out);
}

// round 13
// speedup vs baseline: 1.0031x; 1.0031x over previous
#include <cuda_runtime.h>
#include <cuda_bf16.h>
#include <mma.h>
#include <cstdint>

using namespace nvcuda;

#define NUSER 50000
#define NITEM 100000
#define NNODE 150000
#define NPAD  150016          // multiple of 512 (293*512)
#define NB_SCAN 293
#define NNZ   2000000
#define D     80              // 64 light + 16 mm, fused (augmented)
#define BATCH 1024
#define NTAIL0 99968          // 781*128

// ---------------- static device scratch (no cudaMalloc allowed) ----------------
// Split fp32 propagation buffers: L = 64-dim light (256B rows, line-aligned),
// M = 16-dim mm (64B rows, sector-aligned). Layer 0 = raw inputs (not materialized).
__device__ __align__(256) float g_L1[(size_t)NPAD * 64];
__device__ __align__(256) float g_L2[(size_t)NPAD * 64];
__device__ __align__(256) float g_L3[(size_t)NPAD * 64];
__device__ __align__(256) float g_M1[(size_t)NPAD * 16];
__device__ __align__(256) float g_M2[(size_t)NPAD * 16];
__device__ __align__(256) float g_M3[(size_t)NPAD * 16];
__device__ int   g_cnt[NPAD];          // zero at start; re-zeroed by k_scan_block
__device__ int   g_rowptr[NPAD + 1];
__device__ int   g_cursor[NPAD];
__device__ int   g_bsum[512];
__device__ int   g_boff[512];
__device__ int   g_ci[NNZ];
__device__ float g_cv[NNZ];
__device__ __align__(256) __nv_bfloat16 g_UA[BATCH * D];            // augmented users
__device__ __align__(256) __nv_bfloat16 g_IA[(size_t)NITEM * D];    // augmented items

__device__ __forceinline__ float sigmoidf(float x) {
    return 1.0f / (1.0f + __expf(-x));
}

// ---------------- CSR construction (R5-proven 3-kernel scan) ----------------
__global__ void k_count(const int* __restrict__ rows) {
    int i = blockIdx.x * blockDim.x + threadIdx.x;
    if (i < NNZ) atomicAdd(&g_cnt[rows[i]], 1);
}

// reads counts AND re-zeroes g_cnt for the next replay (k_zero_cnt eliminated)
__global__ void k_scan_block() {
    __shared__ int s[512];
    int t = threadIdx.x;
    int i = blockIdx.x * 512 + t;
    int v = g_cnt[i];
    g_cnt[i] = 0;
    s[t] = v;
    __syncthreads();
    #pragma unroll
    for (int off = 1; off < 512; off <<= 1) {
        int x = (t >= off) ? s[t - off] : 0;
        __syncthreads();
        s[t] += x;
        __syncthreads();
    }
    g_rowptr[i] = s[t] - v;           // block-local exclusive
    if (t == 511) g_bsum[blockIdx.x] = s[511];
}

__global__ void k_scan_bsum() {
    __shared__ int s[512];
    int t = threadIdx.x;
    int v = (t < NB_SCAN) ? g_bsum[t] : 0;
    s[t] = v;
    __syncthreads();
    #pragma unroll
    for (int off = 1; off < 512; off <<= 1) {
        int x = (t >= off) ? s[t - off] : 0;
        __syncthreads();
        s[t] += x;
        __syncthreads();
    }
    g_boff[t] = s[t] - v;             // exclusive
}

__global__ void k_scan_add() {
    int t = threadIdx.x;
    int i = blockIdx.x * 512 + t;
    int r = g_rowptr[i] + g_boff[blockIdx.x];
    g_rowptr[i] = r;
    g_cursor[i] = r;
    if (i == NPAD - 1) g_rowptr[NPAD] = NNZ;
}

__global__ void k_fill(const int* __restrict__ rows, const int* __restrict__ cols,
                       const float* __restrict__ vals) {
    int i = blockIdx.x * blockDim.x + threadIdx.x;
    if (i >= NNZ) return;
    int r = rows[i];
    int p = atomicAdd(&g_cursor[r], 1);
    g_ci[p] = cols[i];
    g_cv[p] = vals[i];
}

// ---------------- layer-0 SpMM: gather directly from input embeddings ----------------
// one row per warp; lane carries float2 of L (64 dims), lanes 0-7 carry float2 of M
__global__ void k_spmm0(const float* __restrict__ eu, const float* __restrict__ ei,
                        const float* __restrict__ mu, const float* __restrict__ mi) {
    int row = blockIdx.x * (blockDim.x >> 5) + (threadIdx.x >> 5);
    int lane = threadIdx.x & 31;
    int start = g_rowptr[row];
    int deg = g_rowptr[row + 1] - start;
    float lx = 0.f, ly = 0.f, mx = 0.f, my = 0.f;
    for (int e = 0; e < deg; e++) {
        int c = __ldg(&g_ci[start + e]);
        float v = __ldg(&g_cv[start + e]);
        const float2 *b64, *b16;
        if (c < NUSER) {
            b64 = (const float2*)(eu + (size_t)c * 64);
            b16 = (const float2*)(mu + (size_t)c * 16);
        } else {
            b64 = (const float2*)(ei + (size_t)(c - NUSER) * 64);
            b16 = (const float2*)(mi + (size_t)(c - NUSER) * 16);
        }
        float2 l = __ldg(b64 + lane);
        lx += v * l.x;
        ly += v * l.y;
        if (lane < 8) {
            float2 m = __ldg(b16 + lane);
            mx += v * m.x;
            my += v * m.y;
        }
    }
    ((float2*)g_L1)[(size_t)row * 32 + lane] = make_float2(lx, ly);
    if (lane < 8)
        ((float2*)g_M1)[(size_t)row * 8 + lane] = make_float2(mx, my);
}

// ---------------- layers 1-2 SpMM: split aligned arrays ----------------
__global__ void k_spmm(const float* __restrict__ Lin, const float* __restrict__ Min,
                       float* __restrict__ Lout, float* __restrict__ Mout) {
    int row = blockIdx.x * (blockDim.x >> 5) + (threadIdx.x >> 5);
    int lane = threadIdx.x & 31;
    int start = g_rowptr[row];
    int deg = g_rowptr[row + 1] - start;
    const float2* __restrict__ L2p = (const float2*)Lin;
    const float2* __restrict__ M2p = (const float2*)Min;
    float lx = 0.f, ly = 0.f, mx = 0.f, my = 0.f;
    for (int e = 0; e < deg; e++) {
        int c = __ldg(&g_ci[start + e]);
        float v = __ldg(&g_cv[start + e]);
        float2 l = __ldg(L2p + (size_t)c * 32 + lane);
        lx += v * l.x;
        ly += v * l.y;
        if (lane < 8) {
            float2 m = __ldg(M2p + (size_t)c * 8 + lane);
            mx += v * m.x;
            my += v * m.y;
        }
    }
    ((float2*)Lout)[(size_t)row * 32 + lane] = make_float2(lx, ly);
    if (lane < 8)
        ((float2*)Mout)[(size_t)row * 8 + lane] = make_float2(mx, my);
}

// ---------------- augmented user / item builders (bf16, /4 folded in) ----------------
__global__ void k_uaug(const int* __restrict__ users, const float* __restrict__ bias_user,
                       const float* __restrict__ eu, const float* __restrict__ mu) {
    int i = blockIdx.x * blockDim.x + threadIdx.x;
    if (i >= BATCH * D) return;
    int b = i / D, d = i % D;
    int u = users[b];
    float v;
    if (d < 64) {
        size_t ol = (size_t)u * 64 + d;
        size_t om = (size_t)u * 16 + (d >> 2);
        float sl = __ldg(eu + ol) + g_L1[ol] + g_L2[ol] + g_L3[ol];
        float sm = __ldg(mu + om) + g_M1[om] + g_M2[om] + g_M3[om];
        v = 0.25f * (sl + sm);
    } else if (d == 64) v = bias_user[u];
    else if (d == 65) v = 1.0f;
    else v = 0.0f;
    g_UA[i] = __float2bfloat16(v);
}

__global__ void k_iaug(const float* __restrict__ bias_item,
                       const float* __restrict__ ei, const float* __restrict__ mi) {
    int i = blockIdx.x * blockDim.x + threadIdx.x;
    if (i >= NITEM * D) return;
    int it = i / D, d = i % D;
    float v;
    if (d < 64) {
        size_t ol = (size_t)(NUSER + it) * 64 + d;
        size_t om = (size_t)(NUSER + it) * 16 + (d >> 2);
        float sl = __ldg(ei + (size_t)it * 64 + d) + g_L1[ol] + g_L2[ol] + g_L3[ol];
        float sm = __ldg(mi + (size_t)it * 16 + (d >> 2)) + g_M1[om] + g_M2[om] + g_M3[om];
        v = 0.25f * (sl + sm);
    } else if (d == 64) v = 1.0f;
    else if (d == 65) v = bias_item[it];
    else v = 0.0f;
    g_IA[i] = __float2bfloat16(v);
}

// ---------------- GEMM: [1024,80]bf16 x [N,80]bf16^T -> sigmoid -> f32 (R5-proven) ----------------
__global__ void __launch_bounds__(256) k_gemm(float* __restrict__ out) {
    __shared__ alignas(16) __nv_bfloat16 As[128][88];
    __shared__ alignas(16) __nv_bfloat16 Bs[128][88];
    int m0 = blockIdx.y * 128;
    int n0 = blockIdx.x * 128;
    int t = threadIdx.x;

    const uint4* ua = (const uint4*)g_UA;   // 10 uint4 per row (80 bf16 = 160B)
    const uint4* ia = (const uint4*)g_IA;
    #pragma unroll
    for (int idx = t; idx < 1280; idx += 256) {
        int r = idx / 10, c = idx % 10;
        *(uint4*)(&As[r][c * 8]) = ua[(size_t)(m0 + r) * 10 + c];
    }
    #pragma unroll
    for (int idx = t; idx < 1280; idx += 256) {
        int r = idx / 10, c = idx % 10;
        *(uint4*)(&Bs[r][c * 8]) = ia[(size_t)(n0 + r) * 10 + c];
    }
    __syncthreads();

    int w = t >> 5;
    int wm = (w >> 1) * 32;   // 0,32,64,96
    int wn = (w & 1) * 64;    // 0,64

    wmma::fragment<wmma::accumulator, 16, 16, 16, float> acc[2][4];
    #pragma unroll
    for (int i = 0; i < 2; i++)
        #pragma unroll
        for (int j = 0; j < 4; j++)
            wmma::fill_fragment(acc[i][j], 0.0f);

    #pragma unroll
    for (int k = 0; k < 80; k += 16) {
        wmma::fragment<wmma::matrix_a, 16, 16, 16, __nv_bfloat16, wmma::row_major> a[2];
        wmma::fragment<wmma::matrix_b, 16, 16, 16, __nv_bfloat16, wmma::col_major> b[4];
        #pragma unroll
        for (int i = 0; i < 2; i++)
            wmma::load_matrix_sync(a[i], &As[wm + 16 * i][0] + k, 88);
        #pragma unroll
        for (int j = 0; j < 4; j++)
            wmma::load_matrix_sync(b[j], &Bs[wn + 16 * j][0] + k, 88);
        #pragma unroll
        for (int i = 0; i < 2; i++)
            #pragma unroll
            for (int j = 0; j < 4; j++)
                wmma::mma_sync(acc[i][j], a[i], b[j], acc[i][j]);
    }

    #pragma unroll
    for (int i = 0; i < 2; i++) {
        #pragma unroll
        for (int j = 0; j < 4; j++) {
            #pragma unroll
            for (int e = 0; e < acc[i][j].num_elements; e++)
                acc[i][j].x[e] = sigmoidf(acc[i][j].x[e]);
            wmma::store_matrix_sync(
                out + (size_t)(m0 + wm + 16 * i) * NITEM + (n0 + wn + 16 * j),
                acc[i][j], NITEM, wmma::mem_row_major);
        }
    }
}

// ---------------- tail: columns [99968, 100000) ----------------
__global__ void k_tail(float* __restrict__ out) {
    int i = blockIdx.x * blockDim.x + threadIdx.x;
    if (i >= BATCH * 32) return;
    int b = i >> 5, j = i & 31;
    int n = NTAIL0 + j;
    const __nv_bfloat16* u = g_UA + (size_t)b * D;
    const __nv_bfloat16* v = g_IA + (size_t)n * D;
    float s = 0.f;
    #pragma unroll
    for (int k = 0; k < D; k++)
        s += __bfloat162float(u[k]) * __bfloat162float(v[k]);
    out[(size_t)b * NITEM + n] = sigmoidf(s);
}

// ---------------- launcher ----------------
extern "C" void kernel_launch(void* const* d_in, const int* in_sizes, int n_in,
                              void* d_out, int out_size) {
    const float* emb_user  = (const float*)d_in[0];
    const float* emb_item  = (const float*)d_in[1];
    const float* bias_user = (const float*)d_in[2];
    const float* bias_item = (const float*)d_in[3];
    const float* mm_user   = (const float*)d_in[4];
    const float* mm_item   = (const float*)d_in[5];
    const float* vals      = (const float*)d_in[6];
    const int*   users     = (const int*)d_in[7];
    const int*   rows      = (const int*)d_in[8];
    const int*   cols      = (const int*)d_in[9];
    float* out = (float*)d_out;

    // CSR build (g_cnt zero on entry; k_scan_block re-zeroes it for the next replay)
    k_count<<<(NNZ + 255) / 256, 256>>>(rows);
    k_scan_block<<<NB_SCAN, 512>>>();
    k_scan_bsum<<<1, 512>>>();
    k_scan_add<<<NB_SCAN, 512>>>();
    k_fill<<<(NNZ + 255) / 256, 256>>>(rows, cols, vals);

    // 3 propagation layers; layer 0 gathers straight from the input embeddings
    k_spmm0<<<NPAD / 8, 256>>>(emb_user, emb_item, mm_user, mm_item);
    k_spmm<<<NPAD / 8, 256>>>(g_L1, g_M1, g_L2, g_M2);
    k_spmm<<<NPAD / 8, 256>>>(g_L2, g_M2, g_L3, g_M3);

    // augmented embeddings (layer-0 term read from raw inputs)
    k_uaug<<<(BATCH * D + 255) / 256, 256>>>(users, bias_user, emb_user, mm_user);
    k_iaug<<<(NITEM * D + 255) / 256, 256>>>(bias_item, emb_item, mm_item);

    // main GEMM + tail
    dim3 grid(NTAIL0 / 128, BATCH / 128);
    k_gemm<<<grid, 256>>>(out);
    k_tail<<<(BATCH * 32 + 255) / 256, 256>>>(out);
}

// round 15
// speedup vs baseline: 11.1952x; 11.1607x over previous
#include <cuda_runtime.h>
#include <cuda_bf16.h>
#include <mma.h>
#include <cstdint>

using namespace nvcuda;

#define NUSER 50000
#define NITEM 100000
#define NNODE 150000
#define NPAD  150016          // multiple of 512 (293*512)
#define NB_SCAN 293
#define NNZ   2000000
#define D     80              // 64 light + 16 mm, fused (augmented)
#define BATCH 1024
#define NTAIL0 99968          // 781*128

// ---------------- static device scratch (no cudaMalloc allowed) ----------------
// Split fp32 propagation buffers: L = 64-dim light (256B rows, line-aligned),
// M = 16-dim mm (64B rows, sector-aligned). Layer 0 = raw inputs (not materialized).
// NOTE: these symbols are ONLY referenced from device code (never as kernel args).
__device__ __align__(256) float g_L1[(size_t)NPAD * 64];
__device__ __align__(256) float g_L2[(size_t)NPAD * 64];
__device__ __align__(256) float g_L3[(size_t)NPAD * 64];
__device__ __align__(256) float g_M1[(size_t)NPAD * 16];
__device__ __align__(256) float g_M2[(size_t)NPAD * 16];
__device__ __align__(256) float g_M3[(size_t)NPAD * 16];
__device__ int   g_cnt[NPAD];          // zero at start; re-zeroed by k_scan_block
__device__ int   g_rowptr[NPAD + 1];
__device__ int   g_cursor[NPAD];
__device__ int   g_bsum[512];
__device__ int   g_boff[512];
__device__ __align__(256) int2 g_edge[NNZ];          // (col, bitcast(val))
__device__ __align__(256) __nv_bfloat16 g_UA[BATCH * D];            // augmented users
__device__ __align__(256) __nv_bfloat16 g_IA[(size_t)NITEM * D];    // augmented items

__device__ __forceinline__ float sigmoidf(float x) {
    return 1.0f / (1.0f + __expf(-x));
}

// ---------------- CSR construction (proven 3-kernel scan) ----------------
__global__ void k_count(const int* __restrict__ rows) {
    int i = blockIdx.x * blockDim.x + threadIdx.x;
    if (i < NNZ) atomicAdd(&g_cnt[rows[i]], 1);
}

// reads counts AND re-zeroes g_cnt for the next replay
__global__ void k_scan_block() {
    __shared__ int s[512];
    int t = threadIdx.x;
    int i = blockIdx.x * 512 + t;
    int v = g_cnt[i];
    g_cnt[i] = 0;
    s[t] = v;
    __syncthreads();
    #pragma unroll
    for (int off = 1; off < 512; off <<= 1) {
        int x = (t >= off) ? s[t - off] : 0;
        __syncthreads();
        s[t] += x;
        __syncthreads();
    }
    g_rowptr[i] = s[t] - v;           // block-local exclusive
    if (t == 511) g_bsum[blockIdx.x] = s[511];
}

__global__ void k_scan_bsum() {
    __shared__ int s[512];
    int t = threadIdx.x;
    int v = (t < NB_SCAN) ? g_bsum[t] : 0;
    s[t] = v;
    __syncthreads();
    #pragma unroll
    for (int off = 1; off < 512; off <<= 1) {
        int x = (t >= off) ? s[t - off] : 0;
        __syncthreads();
        s[t] += x;
        __syncthreads();
    }
    g_boff[t] = s[t] - v;             // exclusive
}

__global__ void k_scan_add() {
    int t = threadIdx.x;
    int i = blockIdx.x * 512 + t;
    int r = g_rowptr[i] + g_boff[blockIdx.x];
    g_rowptr[i] = r;
    g_cursor[i] = r;
    if (i == NPAD - 1) g_rowptr[NPAD] = NNZ;
}

__global__ void k_fill(const int* __restrict__ rows, const int* __restrict__ cols,
                       const float* __restrict__ vals) {
    int i = blockIdx.x * blockDim.x + threadIdx.x;
    if (i >= NNZ) return;
    int r = rows[i];
    int p = atomicAdd(&g_cursor[r], 1);
    g_edge[p] = make_int2(cols[i], __float_as_int(vals[i]));
}

// ---------------- layer-0 SpMM: gather directly from input embeddings ----------------
// one row per warp; warp-cooperative edge fetch (coalesced int2 + shfl broadcast)
__global__ void k_spmm0(const float* __restrict__ eu, const float* __restrict__ ei,
                        const float* __restrict__ mu, const float* __restrict__ mi) {
    int row = blockIdx.x * (blockDim.x >> 5) + (threadIdx.x >> 5);
    int lane = threadIdx.x & 31;
    int start = g_rowptr[row];
    int end = g_rowptr[row + 1];
    float lx = 0.f, ly = 0.f, mx = 0.f, my = 0.f;

    for (int base = start; base < end; base += 32) {
        int n = min(32, end - base);
        int2 ed = make_int2(0, 0);
        if (lane < n) ed = __ldg(&g_edge[base + lane]);
        #pragma unroll 4
        for (int j = 0; j < n; j++) {
            int c = __shfl_sync(0xFFFFFFFFu, ed.x, j);
            float v = __int_as_float(__shfl_sync(0xFFFFFFFFu, ed.y, j));
            const float2 *b64, *b16;
            if (c < NUSER) {
                b64 = (const float2*)(eu + (size_t)c * 64);
                b16 = (const float2*)(mu + (size_t)c * 16);
            } else {
                b64 = (const float2*)(ei + (size_t)(c - NUSER) * 64);
                b16 = (const float2*)(mi + (size_t)(c - NUSER) * 16);
            }
            float2 l = __ldg(b64 + lane);
            lx += v * l.x;
            ly += v * l.y;
            if (lane < 8) {
                float2 m = __ldg(b16 + lane);
                mx += v * m.x;
                my += v * m.y;
            }
        }
    }
    ((float2*)g_L1)[(size_t)row * 32 + lane] = make_float2(lx, ly);
    if (lane < 8)
        ((float2*)g_M1)[(size_t)row * 8 + lane] = make_float2(mx, my);
}

// ---------------- layers 1-2 SpMM: buffers resolved IN DEVICE CODE (int arg) ----------------
__global__ void k_spmm(int layer) {
    const float2* __restrict__ Lin;
    const float2* __restrict__ Min;
    float2* __restrict__ Lout;
    float2* __restrict__ Mout;
    if (layer == 1) {
        Lin = (const float2*)g_L1; Min = (const float2*)g_M1;
        Lout = (float2*)g_L2;      Mout = (float2*)g_M2;
    } else {
        Lin = (const float2*)g_L2; Min = (const float2*)g_M2;
        Lout = (float2*)g_L3;      Mout = (float2*)g_M3;
    }

    int row = blockIdx.x * (blockDim.x >> 5) + (threadIdx.x >> 5);
    int lane = threadIdx.x & 31;
    int start = g_rowptr[row];
    int end = g_rowptr[row + 1];
    float lx = 0.f, ly = 0.f, mx = 0.f, my = 0.f;

    for (int base = start; base < end; base += 32) {
        int n = min(32, end - base);
        int2 ed = make_int2(0, 0);
        if (lane < n) ed = __ldg(&g_edge[base + lane]);
        #pragma unroll 4
        for (int j = 0; j < n; j++) {
            int c = __shfl_sync(0xFFFFFFFFu, ed.x, j);
            float v = __int_as_float(__shfl_sync(0xFFFFFFFFu, ed.y, j));
            float2 l = __ldg(Lin + (size_t)c * 32 + lane);
            lx += v * l.x;
            ly += v * l.y;
            if (lane < 8) {
                float2 m = __ldg(Min + (size_t)c * 8 + lane);
                mx += v * m.x;
                my += v * m.y;
            }
        }
    }
    Lout[(size_t)row * 32 + lane] = make_float2(lx, ly);
    if (lane < 8)
        Mout[(size_t)row * 8 + lane] = make_float2(mx, my);
}

// ---------------- augmented user / item builders (bf16, /4 folded in) ----------------
__global__ void k_uaug(const int* __restrict__ users, const float* __restrict__ bias_user,
                       const float* __restrict__ eu, const float* __restrict__ mu) {
    int i = blockIdx.x * blockDim.x + threadIdx.x;
    if (i >= BATCH * D) return;
    int b = i / D, d = i % D;
    int u = users[b];
    float v;
    if (d < 64) {
        size_t ol = (size_t)u * 64 + d;
        size_t om = (size_t)u * 16 + (d >> 2);
        float sl = __ldg(eu + ol) + g_L1[ol] + g_L2[ol] + g_L3[ol];
        float sm = __ldg(mu + om) + g_M1[om] + g_M2[om] + g_M3[om];
        v = 0.25f * (sl + sm);
    } else if (d == 64) v = bias_user[u];
    else if (d == 65) v = 1.0f;
    else v = 0.0f;
    g_UA[i] = __float2bfloat16(v);
}

__global__ void k_iaug(const float* __restrict__ bias_item,
                       const float* __restrict__ ei, const float* __restrict__ mi) {
    int i = blockIdx.x * blockDim.x + threadIdx.x;
    if (i >= NITEM * D) return;
    int it = i / D, d = i % D;
    float v;
    if (d < 64) {
        size_t ol = (size_t)(NUSER + it) * 64 + d;
        size_t om = (size_t)(NUSER + it) * 16 + (d >> 2);
        float sl = __ldg(ei + (size_t)it * 64 + d) + g_L1[ol] + g_L2[ol] + g_L3[ol];
        float sm = __ldg(mi + (size_t)it * 16 + (d >> 2)) + g_M1[om] + g_M2[om] + g_M3[om];
        v = 0.25f * (sl + sm);
    } else if (d == 64) v = 1.0f;
    else if (d == 65) v = bias_item[it];
    else v = 0.0f;
    g_IA[i] = __float2bfloat16(v);
}

// ---------------- GEMM: [1024,80]bf16 x [N,80]bf16^T -> sigmoid -> f32 (R5-proven) ----------------
__global__ void __launch_bounds__(256) k_gemm(float* __restrict__ out) {
    __shared__ alignas(16) __nv_bfloat16 As[128][88];
    __shared__ alignas(16) __nv_bfloat16 Bs[128][88];
    int m0 = blockIdx.y * 128;
    int n0 = blockIdx.x * 128;
    int t = threadIdx.x;

    const uint4* ua = (const uint4*)g_UA;   // 10 uint4 per row (80 bf16 = 160B)
    const uint4* ia = (const uint4*)g_IA;
    #pragma unroll
    for (int idx = t; idx < 1280; idx += 256) {
        int r = idx / 10, c = idx % 10;
        *(uint4*)(&As[r][c * 8]) = ua[(size_t)(m0 + r) * 10 + c];
    }
    #pragma unroll
    for (int idx = t; idx < 1280; idx += 256) {
        int r = idx / 10, c = idx % 10;
        *(uint4*)(&Bs[r][c * 8]) = ia[(size_t)(n0 + r) * 10 + c];
    }
    __syncthreads();

    int w = t >> 5;
    int wm = (w >> 1) * 32;   // 0,32,64,96
    int wn = (w & 1) * 64;    // 0,64

    wmma::fragment<wmma::accumulator, 16, 16, 16, float> acc[2][4];
    #pragma unroll
    for (int i = 0; i < 2; i++)
        #pragma unroll
        for (int j = 0; j < 4; j++)
            wmma::fill_fragment(acc[i][j], 0.0f);

    #pragma unroll
    for (int k = 0; k < 80; k += 16) {
        wmma::fragment<wmma::matrix_a, 16, 16, 16, __nv_bfloat16, wmma::row_major> a[2];
        wmma::fragment<wmma::matrix_b, 16, 16, 16, __nv_bfloat16, wmma::col_major> b[4];
        #pragma unroll
        for (int i = 0; i < 2; i++)
            wmma::load_matrix_sync(a[i], &As[wm + 16 * i][0] + k, 88);
        #pragma unroll
        for (int j = 0; j < 4; j++)
            wmma::load_matrix_sync(b[j], &Bs[wn + 16 * j][0] + k, 88);
        #pragma unroll
        for (int i = 0; i < 2; i++)
            #pragma unroll
            for (int j = 0; j < 4; j++)
                wmma::mma_sync(acc[i][j], a[i], b[j], acc[i][j]);
    }

    #pragma unroll
    for (int i = 0; i < 2; i++) {
        #pragma unroll
        for (int j = 0; j < 4; j++) {
            #pragma unroll
            for (int e = 0; e < acc[i][j].num_elements; e++)
                acc[i][j].x[e] = sigmoidf(acc[i][j].x[e]);
            wmma::store_matrix_sync(
                out + (size_t)(m0 + wm + 16 * i) * NITEM + (n0 + wn + 16 * j),
                acc[i][j], NITEM, wmma::mem_row_major);
        }
    }
}

// ---------------- tail: columns [99968, 100000) ----------------
__global__ void k_tail(float* __restrict__ out) {
    int i = blockIdx.x * blockDim.x + threadIdx.x;
    if (i >= BATCH * 32) return;
    int b = i >> 5, j = i & 31;
    int n = NTAIL0 + j;
    const __nv_bfloat16* u = g_UA + (size_t)b * D;
    const __nv_bfloat16* v = g_IA + (size_t)n * D;
    float s = 0.f;
    #pragma unroll
    for (int k = 0; k < D; k++)
        s += __bfloat162float(u[k]) * __bfloat162float(v[k]);
    out[(size_t)b * NITEM + n] = sigmoidf(s);
}

// ---------------- launcher ----------------
extern "C" void kernel_launch(void* const* d_in, const int* in_sizes, int n_in,
                              void* d_out, int out_size) {
    const float* emb_user  = (const float*)d_in[0];
    const float* emb_item  = (const float*)d_in[1];
    const float* bias_user = (const float*)d_in[2];
    const float* bias_item = (const float*)d_in[3];
    const float* mm_user   = (const float*)d_in[4];
    const float* mm_item   = (const float*)d_in[5];
    const float* vals      = (const float*)d_in[6];
    const int*   users     = (const int*)d_in[7];
    const int*   rows      = (const int*)d_in[8];
    const int*   cols      = (const int*)d_in[9];
    float* out = (float*)d_out;

    // CSR build (g_cnt zero on entry; k_scan_block re-zeroes it for the next replay)
    k_count<<<(NNZ + 255) / 256, 256>>>(rows);
    k_scan_block<<<NB_SCAN, 512>>>();
    k_scan_bsum<<<1, 512>>>();
    k_scan_add<<<NB_SCAN, 512>>>();
    k_fill<<<(NNZ + 255) / 256, 256>>>(rows, cols, vals);

    // 3 propagation layers; layer 0 gathers straight from the input embeddings.
    // Buffer selection for layers 1-2 happens in DEVICE code (int arg), never via
    // host-side __device__ symbol decay (GB300/ATS silently maps that to host memory).
    k_spmm0<<<NPAD / 8, 256>>>(emb_user, emb_item, mm_user, mm_item);
    k_spmm<<<NPAD / 8, 256>>>(1);
    k_spmm<<<NPAD / 8, 256>>>(2);

    // augmented embeddings (layer-0 term read from raw inputs)
    k_uaug<<<(BATCH * D + 255) / 256, 256>>>(users, bias_user, emb_user, mm_user);
    k_iaug<<<(NITEM * D + 255) / 256, 256>>>(bias_item, emb_item, mm_item);

    // main GEMM + tail
    dim3 grid(NTAIL0 / 128, BATCH / 128);
    k_gemm<<<grid, 256>>>(out);
    k_tail<<<(BATCH * 32 + 255) / 256, 256>>>(out);
}

// round 17
// speedup vs baseline: 13.7235x; 1.2258x over previous
#include <cuda_runtime.h>
#include <cuda_bf16.h>
#include <mma.h>
#include <cstdint>

using namespace nvcuda;

#define NUSER 50000
#define NITEM 100000
#define NNODE 150000
#define NPAD  150016          // multiple of 512 (293*512)
#define NB_SCAN 293
#define NNZ   2000000
#define D     80              // 64 light + 16 mm, fused
#define BATCH 1024
#define NTAIL0 99968          // 781*128

// ---------------- static device scratch (no cudaMalloc allowed) ----------------
// Only referenced from device code (never passed as kernel args from host).
__device__ __align__(256) float g_X0[(size_t)NPAD * D];
__device__ __align__(256) float g_X1[(size_t)NPAD * D];
__device__ __align__(256) float g_X2[(size_t)NPAD * D];
__device__ int   g_cnt[NPAD];          // zero at start; re-zeroed by k_scan_block
__device__ int   g_rowptr[NPAD + 1];
__device__ int   g_cursor[NPAD];
__device__ int   g_bsum[512];
__device__ int   g_boff[512];
__device__ int   g_ci[NNZ];
__device__ float g_cv[NNZ];
__device__ __align__(256) __nv_bfloat16 g_UA[BATCH * D];            // augmented users
__device__ __align__(256) __nv_bfloat16 g_IA[(size_t)NITEM * D];    // augmented items

__device__ __forceinline__ float sigmoidf(float x) {
    return 1.0f / (1.0f + __expf(-x));
}

// ---------------- CSR construction (R5-proven 3-kernel scan) ----------------
__global__ void k_count(const int* __restrict__ rows) {
    int i = blockIdx.x * blockDim.x + threadIdx.x;
    if (i < NNZ) atomicAdd(&g_cnt[rows[i]], 1);
}

// reads counts AND re-zeroes g_cnt for the next graph replay
__global__ void k_scan_block() {
    __shared__ int s[512];
    int t = threadIdx.x;
    int i = blockIdx.x * 512 + t;
    int v = g_cnt[i];
    g_cnt[i] = 0;
    s[t] = v;
    __syncthreads();
    #pragma unroll
    for (int off = 1; off < 512; off <<= 1) {
        int x = (t >= off) ? s[t - off] : 0;
        __syncthreads();
        s[t] += x;
        __syncthreads();
    }
    g_rowptr[i] = s[t] - v;           // block-local exclusive
    if (t == 511) g_bsum[blockIdx.x] = s[511];
}

__global__ void k_scan_bsum() {
    __shared__ int s[512];
    int t = threadIdx.x;
    int v = (t < NB_SCAN) ? g_bsum[t] : 0;
    s[t] = v;
    __syncthreads();
    #pragma unroll
    for (int off = 1; off < 512; off <<= 1) {
        int x = (t >= off) ? s[t - off] : 0;
        __syncthreads();
        s[t] += x;
        __syncthreads();
    }
    g_boff[t] = s[t] - v;             // exclusive
}

__global__ void k_scan_add() {
    int t = threadIdx.x;
    int i = blockIdx.x * 512 + t;
    int r = g_rowptr[i] + g_boff[blockIdx.x];
    g_rowptr[i] = r;
    g_cursor[i] = r;
    if (i == NPAD - 1) g_rowptr[NPAD] = NNZ;
}

__global__ void k_fill(const int* __restrict__ rows, const int* __restrict__ cols,
                       const float* __restrict__ vals) {
    int i = blockIdx.x * blockDim.x + threadIdx.x;
    if (i >= NNZ) return;
    int r = rows[i];
    int p = atomicAdd(&g_cursor[r], 1);
    g_ci[p] = cols[i];
    g_cv[p] = vals[i];
}

// ---------------- init X0 = concat(emb, mm_emb) (R5-proven) ----------------
__global__ void k_init(const float* __restrict__ eu, const float* __restrict__ ei,
                       const float* __restrict__ mu, const float* __restrict__ mi) {
    int i = blockIdx.x * blockDim.x + threadIdx.x;
    if (i >= NNODE * D) return;
    int n = i / D, d = i % D;
    float v;
    if (n < NUSER) {
        v = (d < 64) ? eu[n * 64 + d] : mu[n * 16 + (d - 64)];
    } else {
        int m = n - NUSER;
        v = (d < 64) ? ei[m * 64 + d] : mi[m * 16 + (d - 64)];
    }
    g_X0[(size_t)n * D + d] = v;
}

// ---------------- layers 0-1 SpMM: R5-proven gather, one row per warp ----------------
// layer 0: X0 -> X1 ; layer 1: X1 -> X2  (buffers resolved in device code)
__global__ void k_spmm(int layer) {
    const float* __restrict__ Xin = (layer == 0) ? g_X0 : g_X1;
    float* __restrict__ Xout = (layer == 0) ? g_X1 : g_X2;
    int row = blockIdx.x * (blockDim.x >> 5) + (threadIdx.x >> 5);
    if (row >= NPAD) return;
    int lane = threadIdx.x & 31;
    int start = g_rowptr[row];
    int deg = g_rowptr[row + 1] - start;
    float a0 = 0.f, a1 = 0.f, a2 = 0.f;
    for (int e = 0; e < deg; e++) {
        int c = __ldg(&g_ci[start + e]);
        float v = __ldg(&g_cv[start + e]);
        const float* xr = Xin + (size_t)c * D;
        a0 += v * __ldg(xr + lane);
        a1 += v * __ldg(xr + 32 + lane);
        if (lane < 16) a2 += v * __ldg(xr + 64 + lane);
    }
    float* o = Xout + (size_t)row * D;
    o[lane] = a0;
    o[32 + lane] = a1;
    if (lane < 16) o[64 + lane] = a2;
}

// ---------------- fused final layer + aug, ITEM rows only ----------------
// gather x3 from X2 for row NUSER+it, add x0+x1+x2, upsample mm, write bf16 g_IA
__global__ void k_spmm3i(const float* __restrict__ bias_item) {
    int it = blockIdx.x * (blockDim.x >> 5) + (threadIdx.x >> 5);
    if (it >= NITEM) return;
    int row = NUSER + it;
    int lane = threadIdx.x & 31;
    int start = g_rowptr[row];
    int deg = g_rowptr[row + 1] - start;
    float a0 = 0.f, a1 = 0.f, a2 = 0.f;
    for (int e = 0; e < deg; e++) {
        int c = __ldg(&g_ci[start + e]);
        float v = __ldg(&g_cv[start + e]);
        const float* xr = g_X2 + (size_t)c * D;
        a0 += v * __ldg(xr + lane);
        a1 += v * __ldg(xr + 32 + lane);
        if (lane < 16) a2 += v * __ldg(xr + 64 + lane);
    }
    size_t o = (size_t)row * D;
    float l0 = g_X0[o + lane] + g_X1[o + lane] + g_X2[o + lane] + a0;
    float l1 = g_X0[o + 32 + lane] + g_X1[o + 32 + lane] + g_X2[o + 32 + lane] + a1;
    float ms = 0.f;
    if (lane < 16)
        ms = g_X0[o + 64 + lane] + g_X1[o + 64 + lane] + g_X2[o + 64 + lane] + a2;
    // upsample_nearest: IA dim d adds mm[d>>2]; d=lane -> lane>>2, d=32+lane -> 8+(lane>>2)
    float m0 = __shfl_sync(0xFFFFFFFFu, ms, lane >> 2);
    float m1 = __shfl_sync(0xFFFFFFFFu, ms, 8 + (lane >> 2));
    __nv_bfloat16* dst = g_IA + (size_t)it * D;
    dst[lane] = __float2bfloat16(0.25f * (l0 + m0));
    dst[32 + lane] = __float2bfloat16(0.25f * (l1 + m1));
    if (lane == 0) {
        dst[64] = __float2bfloat16(1.0f);
        dst[65] = __float2bfloat16(__ldg(bias_item + it));
    }
    // dims 66..79 remain zero (static zero-init; no kernel ever writes them)
}

// ---------------- fused final layer + aug, batch USER rows only (1024 warps) ----------------
__global__ void k_spmm3u(const int* __restrict__ users, const float* __restrict__ bias_user) {
    int b = blockIdx.x * (blockDim.x >> 5) + (threadIdx.x >> 5);
    if (b >= BATCH) return;
    int lane = threadIdx.x & 31;
    int row = __ldg(users + b);
    int start = g_rowptr[row];
    int deg = g_rowptr[row + 1] - start;
    float a0 = 0.f, a1 = 0.f, a2 = 0.f;
    for (int e = 0; e < deg; e++) {
        int c = __ldg(&g_ci[start + e]);
        float v = __ldg(&g_cv[start + e]);
        const float* xr = g_X2 + (size_t)c * D;
        a0 += v * __ldg(xr + lane);
        a1 += v * __ldg(xr + 32 + lane);
        if (lane < 16) a2 += v * __ldg(xr + 64 + lane);
    }
    size_t o = (size_t)row * D;
    float l0 = g_X0[o + lane] + g_X1[o + lane] + g_X2[o + lane] + a0;
    float l1 = g_X0[o + 32 + lane] + g_X1[o + 32 + lane] + g_X2[o + 32 + lane] + a1;
    float ms = 0.f;
    if (lane < 16)
        ms = g_X0[o + 64 + lane] + g_X1[o + 64 + lane] + g_X2[o + 64 + lane] + a2;
    float m0 = __shfl_sync(0xFFFFFFFFu, ms, lane >> 2);
    float m1 = __shfl_sync(0xFFFFFFFFu, ms, 8 + (lane >> 2));
    __nv_bfloat16* dst = g_UA + (size_t)b * D;
    dst[lane] = __float2bfloat16(0.25f * (l0 + m0));
    dst[32 + lane] = __float2bfloat16(0.25f * (l1 + m1));
    if (lane == 0) {
        dst[64] = __float2bfloat16(__ldg(bias_user + row));
        dst[65] = __float2bfloat16(1.0f);
    }
}

// ---------------- GEMM: [1024,80]bf16 x [N,80]bf16^T -> sigmoid -> f32 (R5-proven) ----------------
__global__ void __launch_bounds__(256) k_gemm(float* __restrict__ out) {
    __shared__ alignas(16) __nv_bfloat16 As[128][88];
    __shared__ alignas(16) __nv_bfloat16 Bs[128][88];
    int m0 = blockIdx.y * 128;
    int n0 = blockIdx.x * 128;
    int t = threadIdx.x;

    const uint4* ua = (const uint4*)g_UA;   // 10 uint4 per row (80 bf16 = 160B)
    const uint4* ia = (const uint4*)g_IA;
    #pragma unroll
    for (int idx = t; idx < 1280; idx += 256) {
        int r = idx / 10, c = idx % 10;
        *(uint4*)(&As[r][c * 8]) = ua[(size_t)(m0 + r) * 10 + c];
    }
    #pragma unroll
    for (int idx = t; idx < 1280; idx += 256) {
        int r = idx / 10, c = idx % 10;
        *(uint4*)(&Bs[r][c * 8]) = ia[(size_t)(n0 + r) * 10 + c];
    }
    __syncthreads();

    int w = t >> 5;
    int wm = (w >> 1) * 32;   // 0,32,64,96
    int wn = (w & 1) * 64;    // 0,64

    wmma::fragment<wmma::accumulator, 16, 16, 16, float> acc[2][4];
    #pragma unroll
    for (int i = 0; i < 2; i++)
        #pragma unroll
        for (int j = 0; j < 4; j++)
            wmma::fill_fragment(acc[i][j], 0.0f);

    #pragma unroll
    for (int k = 0; k < 80; k += 16) {
        wmma::fragment<wmma::matrix_a, 16, 16, 16, __nv_bfloat16, wmma::row_major> a[2];
        wmma::fragment<wmma::matrix_b, 16, 16, 16, __nv_bfloat16, wmma::col_major> b[4];
        #pragma unroll
        for (int i = 0; i < 2; i++)
            wmma::load_matrix_sync(a[i], &As[wm + 16 * i][0] + k, 88);
        #pragma unroll
        for (int j = 0; j < 4; j++)
            wmma::load_matrix_sync(b[j], &Bs[wn + 16 * j][0] + k, 88);
        #pragma unroll
        for (int i = 0; i < 2; i++)
            #pragma unroll
            for (int j = 0; j < 4; j++)
                wmma::mma_sync(acc[i][j], a[i], b[j], acc[i][j]);
    }

    #pragma unroll
    for (int i = 0; i < 2; i++) {
        #pragma unroll
        for (int j = 0; j < 4; j++) {
            #pragma unroll
            for (int e = 0; e < acc[i][j].num_elements; e++)
                acc[i][j].x[e] = sigmoidf(acc[i][j].x[e]);
            wmma::store_matrix_sync(
                out + (size_t)(m0 + wm + 16 * i) * NITEM + (n0 + wn + 16 * j),
                acc[i][j], NITEM, wmma::mem_row_major);
        }
    }
}

// ---------------- tail: columns [99968, 100000) ----------------
__global__ void k_tail(float* __restrict__ out) {
    int i = blockIdx.x * blockDim.x + threadIdx.x;
    if (i >= BATCH * 32) return;
    int b = i >> 5, j = i & 31;
    int n = NTAIL0 + j;
    const __nv_bfloat16* u = g_UA + (size_t)b * D;
    const __nv_bfloat16* v = g_IA + (size_t)n * D;
    float s = 0.f;
    #pragma unroll
    for (int k = 0; k < D; k++)
        s += __bfloat162float(u[k]) * __bfloat162float(v[k]);
    out[(size_t)b * NITEM + n] = sigmoidf(s);
}

// ---------------- launcher ----------------
extern "C" void kernel_launch(void* const* d_in, const int* in_sizes, int n_in,
                              void* d_out, int out_size) {
    const float* emb_user  = (const float*)d_in[0];
    const float* emb_item  = (const float*)d_in[1];
    const float* bias_user = (const float*)d_in[2];
    const float* bias_item = (const float*)d_in[3];
    const float* mm_user   = (const float*)d_in[4];
    const float* mm_item   = (const float*)d_in[5];
    const float* vals      = (const float*)d_in[6];
    const int*   users     = (const int*)d_in[7];
    const int*   rows      = (const int*)d_in[8];
    const int*   cols      = (const int*)d_in[9];
    float* out = (float*)d_out;

    // CSR build (g_cnt zero on entry; k_scan_block re-zeroes it for next replay)
    k_count<<<(NNZ + 255) / 256, 256>>>(rows);
    k_scan_block<<<NB_SCAN, 512>>>();
    k_scan_bsum<<<1, 512>>>();
    k_scan_add<<<NB_SCAN, 512>>>();
    k_fill<<<(NNZ + 255) / 256, 256>>>(rows, cols, vals);

    // X0
    k_init<<<(NNODE * D + 255) / 256, 256>>>(emb_user, emb_item, mm_user, mm_item);

    // layers 0-1: full propagation (X0->X1->X2)
    k_spmm<<<NPAD / 8, 256>>>(0);
    k_spmm<<<NPAD / 8, 256>>>(1);

    // final layer: pruned to needed rows + fused aug epilogue
    k_spmm3u<<<BATCH / 8, 256>>>(users, bias_user);
    k_spmm3i<<<NITEM / 8, 256>>>(bias_item);

    // main GEMM + tail
    dim3 grid(NTAIL0 / 128, BATCH / 128);
    k_gemm<<<grid, 256>>>(out);
    k_tail<<<(BATCH * 32 + 255) / 256, 256>>>(out);
}